// round 3
// baseline (speedup 1.0000x reference)
#include <cuda_runtime.h>

// Problem constants
#define BB 4
#define SS 2048
#define HID 512
#define NH 8
#define DH 64

// Scratch (device globals: allocation-guard-safe). Kernels reference these
// directly — no cudaGetSymbolAddress, no host API calls besides launches.
__device__ float g_qh[BB*NH*SS*DH];          // 16 MB  [b][h][s][d]  (pre-scaled by 1/8)
__device__ float g_kh[BB*NH*SS*DH];          // 16 MB
__device__ float g_vh[BB*NH*SS*DH];          // 16 MB
__device__ float g_attn[BB*SS*HID];          // 16 MB  [b][s][h*64+d]
__device__ float g_biasH[(size_t)BB*NH*SS*SS]; // 537 MB [b][h][q][k]

// ---------------------------------------------------------------------------
// GEMM (NT): C[m,n] = (sum_k A[m,k] * W[n,k] + bias[n]) * scale
// A: [M x 512] row-major, W: [512 x 512] row-major. M = 8192, N = K = 512.
// MODE 0: scatter to g_qh/g_kh/g_vh-style [b][h][s][d] layout (dst param).
// MODE 1: row-major [m][n] (dst param).
// ---------------------------------------------------------------------------
template<int MODE>
__global__ __launch_bounds__(256, 2) void gemm_nt(
    const float* __restrict__ A, const float* __restrict__ W,
    const float* __restrict__ bias, float* __restrict__ C, float scale)
{
    __shared__ __align__(16) float As[16][132];
    __shared__ __align__(16) float Bs[16][132];
    const int tid = threadIdx.x;
    const int tx = tid & 15, ty = tid >> 4;
    const int m0 = blockIdx.y * 128;
    const int n0 = blockIdx.x * 128;

    float acc[8][8];
#pragma unroll
    for (int i = 0; i < 8; i++)
#pragma unroll
        for (int j = 0; j < 8; j++) acc[i][j] = 0.f;

    for (int k0 = 0; k0 < 512; k0 += 16) {
#pragma unroll
        for (int r = 0; r < 2; r++) {
            int f = tid + r * 256;           // 0..511 float4 slots
            int row = f >> 2;                // 0..127
            int c4 = (f & 3) * 4;            // 0,4,8,12
            float4 va = *(const float4*)(A + (m0 + row) * 512 + k0 + c4);
            As[c4 + 0][row] = va.x; As[c4 + 1][row] = va.y;
            As[c4 + 2][row] = va.z; As[c4 + 3][row] = va.w;
            float4 vb = *(const float4*)(W + (n0 + row) * 512 + k0 + c4);
            Bs[c4 + 0][row] = vb.x; Bs[c4 + 1][row] = vb.y;
            Bs[c4 + 2][row] = vb.z; Bs[c4 + 3][row] = vb.w;
        }
        __syncthreads();
#pragma unroll
        for (int kk = 0; kk < 16; kk++) {
            float a[8], b[8];
            *(float4*)&a[0] = *(const float4*)&As[kk][ty * 4];
            *(float4*)&a[4] = *(const float4*)&As[kk][64 + ty * 4];
            *(float4*)&b[0] = *(const float4*)&Bs[kk][tx * 4];
            *(float4*)&b[4] = *(const float4*)&Bs[kk][64 + tx * 4];
#pragma unroll
            for (int i = 0; i < 8; i++)
#pragma unroll
                for (int j = 0; j < 8; j++)
                    acc[i][j] = fmaf(a[i], b[j], acc[i][j]);
        }
        __syncthreads();
    }

#pragma unroll
    for (int mh = 0; mh < 2; mh++)
#pragma unroll
    for (int i = 0; i < 4; i++) {
        int m = m0 + mh * 64 + ty * 4 + i;
#pragma unroll
        for (int nh = 0; nh < 2; nh++) {
            int n = n0 + nh * 64 + tx * 4;
            float4 bv = *(const float4*)(bias + n);
            float4 o;
            o.x = (acc[mh * 4 + i][nh * 4 + 0] + bv.x) * scale;
            o.y = (acc[mh * 4 + i][nh * 4 + 1] + bv.y) * scale;
            o.z = (acc[mh * 4 + i][nh * 4 + 2] + bv.z) * scale;
            o.w = (acc[mh * 4 + i][nh * 4 + 3] + bv.w) * scale;
            if (MODE == 0) {
                int b_ = m >> 11, s_ = m & 2047;
                int h_ = n >> 6,  d_ = n & 63;
                *(float4*)(C + (((b_ * NH + h_) * SS) + s_) * DH + d_) = o;
            } else {
                *(float4*)(C + m * 512 + n) = o;
            }
        }
    }
}

// ---------------------------------------------------------------------------
// Bias projection: g_biasH[b,h,q,k] = bb[h] + sum_d attn_bias[b,q,k,d]*Wb[h,d]
// One thread per (b,q,k).
// ---------------------------------------------------------------------------
__global__ __launch_bounds__(256) void bias_kernel(
    const float* __restrict__ ab, const float* __restrict__ Wb,
    const float* __restrict__ bbv)
{
    __shared__ float wsh[64];
    __shared__ float bsh[8];
    if (threadIdx.x < 64) wsh[threadIdx.x] = Wb[threadIdx.x];
    if (threadIdx.x < 8)  bsh[threadIdx.x] = bbv[threadIdx.x];
    __syncthreads();

    int idx = blockIdx.x * 256 + threadIdx.x;        // < 2^24 = B*S*S
    float4 a0 = *(const float4*)(ab + (size_t)idx * 8);
    float4 a1 = *(const float4*)(ab + (size_t)idx * 8 + 4);
    int b_ = idx >> 22;                 // / (S*S)
    int rem = idx & 4194303;
    int q_ = rem >> 11;
    int k_ = rem & 2047;

#pragma unroll
    for (int h = 0; h < 8; h++) {
        float v = bsh[h];
        v = fmaf(a0.x, wsh[h * 8 + 0], v);
        v = fmaf(a0.y, wsh[h * 8 + 1], v);
        v = fmaf(a0.z, wsh[h * 8 + 2], v);
        v = fmaf(a0.w, wsh[h * 8 + 3], v);
        v = fmaf(a1.x, wsh[h * 8 + 4], v);
        v = fmaf(a1.y, wsh[h * 8 + 5], v);
        v = fmaf(a1.z, wsh[h * 8 + 6], v);
        v = fmaf(a1.w, wsh[h * 8 + 7], v);
        g_biasH[(((size_t)(b_ * NH + h) * SS + q_) * SS) + k_] = v;
    }
}

// ---------------------------------------------------------------------------
// Flash attention: one CTA per (b, h, q-tile of 64). TK = 32.
// Online softmax; q pre-scaled. Writes g_attn in [b][s][h*64+d] layout.
// ---------------------------------------------------------------------------
__global__ __launch_bounds__(256) void attn_kernel()
{
    __shared__ __align__(16) float Qs[64 * 64];   // [d][q]
    __shared__ float Ks[64 * 33];                 // [d][k] padded
    __shared__ __align__(16) float Vs[32 * 64];   // [k][d]
    __shared__ float Ps[64 * 32];                 // [q][k]
    __shared__ float sm_m[64];
    __shared__ float sm_l[64];

    const int tid = threadIdx.x;
    const int tx = tid & 15, ty = tid >> 4;
    const int qt = blockIdx.x & 31;
    const int bh = blockIdx.x >> 5;               // b*8 + h

    const float* qg = g_qh + (bh * SS + qt * 64) * DH;
    const float* kg = g_kh + bh * SS * DH;
    const float* vg = g_vh + bh * SS * DH;
    const float* bg = g_biasH + ((size_t)(bh * SS + qt * 64)) * SS;

    // Load Q tile transposed: Qs[d][q]
#pragma unroll
    for (int r = 0; r < 4; r++) {
        int f = tid + r * 256;
        int row = f >> 4, c4 = (f & 15) * 4;
        float4 v = *(const float4*)(qg + row * 64 + c4);
        Qs[(c4 + 0) * 64 + row] = v.x;
        Qs[(c4 + 1) * 64 + row] = v.y;
        Qs[(c4 + 2) * 64 + row] = v.z;
        Qs[(c4 + 3) * 64 + row] = v.w;
    }
    if (tid < 64) { sm_m[tid] = -1e30f; sm_l[tid] = 0.f; }

    float acc[4][4];
#pragma unroll
    for (int i = 0; i < 4; i++)
#pragma unroll
        for (int j = 0; j < 4; j++) acc[i][j] = 0.f;
    __syncthreads();

    for (int kt = 0; kt < SS; kt += 32) {
        // Load K (transposed, padded) and V (direct)
#pragma unroll
        for (int r = 0; r < 2; r++) {
            int f = tid + r * 256;
            int row = f >> 4, c4 = (f & 15) * 4;
            float4 kv = *(const float4*)(kg + (kt + row) * 64 + c4);
            Ks[(c4 + 0) * 33 + row] = kv.x;
            Ks[(c4 + 1) * 33 + row] = kv.y;
            Ks[(c4 + 2) * 33 + row] = kv.z;
            Ks[(c4 + 3) * 33 + row] = kv.w;
            *(float4*)(Vs + row * 64 + c4) = *(const float4*)(vg + (kt + row) * 64 + c4);
        }
        __syncthreads();

        // Scores: sc[q 4][k 2]
        float sc[4][2];
#pragma unroll
        for (int i = 0; i < 4; i++) { sc[i][0] = 0.f; sc[i][1] = 0.f; }
#pragma unroll
        for (int d = 0; d < 64; d++) {
            float4 a = *(const float4*)&Qs[d * 64 + ty * 4];
            float b0 = Ks[d * 33 + tx * 2];
            float b1 = Ks[d * 33 + tx * 2 + 1];
            sc[0][0] = fmaf(a.x, b0, sc[0][0]); sc[0][1] = fmaf(a.x, b1, sc[0][1]);
            sc[1][0] = fmaf(a.y, b0, sc[1][0]); sc[1][1] = fmaf(a.y, b1, sc[1][1]);
            sc[2][0] = fmaf(a.z, b0, sc[2][0]); sc[2][1] = fmaf(a.z, b1, sc[2][1]);
            sc[3][0] = fmaf(a.w, b0, sc[3][0]); sc[3][1] = fmaf(a.w, b1, sc[3][1]);
        }

        // Bias add + online softmax per q-row (16 lanes per row group)
#pragma unroll
        for (int i = 0; i < 4; i++) {
            int row = ty * 4 + i;
            float2 bv = *(const float2*)(bg + (size_t)row * SS + kt + tx * 2);
            float s0 = sc[i][0] + bv.x;
            float s1 = sc[i][1] + bv.y;
            float mloc = fmaxf(s0, s1);
#pragma unroll
            for (int o = 8; o > 0; o >>= 1)
                mloc = fmaxf(mloc, __shfl_xor_sync(0xffffffffu, mloc, o));
            float mprev = sm_m[row];
            float mtot = fmaxf(mprev, mloc);
            float fac = __expf(mprev - mtot);
            float p0 = __expf(s0 - mtot);
            float p1 = __expf(s1 - mtot);
            float rs = p0 + p1;
#pragma unroll
            for (int o = 8; o > 0; o >>= 1)
                rs += __shfl_xor_sync(0xffffffffu, rs, o);
            if (tx == 0) { sm_m[row] = mtot; sm_l[row] = sm_l[row] * fac + rs; }
#pragma unroll
            for (int j = 0; j < 4; j++) acc[i][j] *= fac;
            Ps[row * 32 + tx * 2]     = p0;
            Ps[row * 32 + tx * 2 + 1] = p1;
        }
        __syncthreads();

        // acc[q][d] += P[q][kk] * V[kk][d]
#pragma unroll
        for (int kk = 0; kk < 32; kk++) {
            float4 vv = *(const float4*)&Vs[kk * 64 + tx * 4];
            float p0 = Ps[(ty * 4 + 0) * 32 + kk];
            float p1 = Ps[(ty * 4 + 1) * 32 + kk];
            float p2 = Ps[(ty * 4 + 2) * 32 + kk];
            float p3 = Ps[(ty * 4 + 3) * 32 + kk];
            acc[0][0] = fmaf(p0, vv.x, acc[0][0]); acc[0][1] = fmaf(p0, vv.y, acc[0][1]);
            acc[0][2] = fmaf(p0, vv.z, acc[0][2]); acc[0][3] = fmaf(p0, vv.w, acc[0][3]);
            acc[1][0] = fmaf(p1, vv.x, acc[1][0]); acc[1][1] = fmaf(p1, vv.y, acc[1][1]);
            acc[1][2] = fmaf(p1, vv.z, acc[1][2]); acc[1][3] = fmaf(p1, vv.w, acc[1][3]);
            acc[2][0] = fmaf(p2, vv.x, acc[2][0]); acc[2][1] = fmaf(p2, vv.y, acc[2][1]);
            acc[2][2] = fmaf(p2, vv.z, acc[2][2]); acc[2][3] = fmaf(p2, vv.w, acc[2][3]);
            acc[3][0] = fmaf(p3, vv.x, acc[3][0]); acc[3][1] = fmaf(p3, vv.y, acc[3][1]);
            acc[3][2] = fmaf(p3, vv.z, acc[3][2]); acc[3][3] = fmaf(p3, vv.w, acc[3][3]);
        }
        __syncthreads();
    }

    // Epilogue: normalize and write to [b][s][h*64+d]
    const int b_ = bh >> 3, h_ = bh & 7;
#pragma unroll
    for (int i = 0; i < 4; i++) {
        int row = ty * 4 + i;
        float inv = 1.f / sm_l[row];
        float4 o;
        o.x = acc[i][0] * inv; o.y = acc[i][1] * inv;
        o.z = acc[i][2] * inv; o.w = acc[i][3] * inv;
        *(float4*)(g_attn + (b_ * SS + qt * 64 + row) * HID + h_ * 64 + tx * 4) = o;
    }
}

// ---------------------------------------------------------------------------
// Thin wrappers so gemm_nt can read/write the device globals without any host
// symbol-address API.
// ---------------------------------------------------------------------------
__global__ __launch_bounds__(256, 2) void gemm_proj(
    const float* __restrict__ A, const float* __restrict__ W,
    const float* __restrict__ bias, int which, float scale);

// Re-dispatch trick kept simple: use a device-side selector inside one kernel.
__global__ __launch_bounds__(256, 2) void gemm_proj_impl(
    const float* __restrict__ A, const float* __restrict__ W,
    const float* __restrict__ bias, int which, float scale)
{
    // which: 0->g_qh, 1->g_kh, 2->g_vh
    float* dst = (which == 0) ? g_qh : (which == 1) ? g_kh : g_vh;

    __shared__ __align__(16) float As[16][132];
    __shared__ __align__(16) float Bs[16][132];
    const int tid = threadIdx.x;
    const int tx = tid & 15, ty = tid >> 4;
    const int m0 = blockIdx.y * 128;
    const int n0 = blockIdx.x * 128;

    float acc[8][8];
#pragma unroll
    for (int i = 0; i < 8; i++)
#pragma unroll
        for (int j = 0; j < 8; j++) acc[i][j] = 0.f;

    for (int k0 = 0; k0 < 512; k0 += 16) {
#pragma unroll
        for (int r = 0; r < 2; r++) {
            int f = tid + r * 256;
            int row = f >> 2;
            int c4 = (f & 3) * 4;
            float4 va = *(const float4*)(A + (m0 + row) * 512 + k0 + c4);
            As[c4 + 0][row] = va.x; As[c4 + 1][row] = va.y;
            As[c4 + 2][row] = va.z; As[c4 + 3][row] = va.w;
            float4 vb = *(const float4*)(W + (n0 + row) * 512 + k0 + c4);
            Bs[c4 + 0][row] = vb.x; Bs[c4 + 1][row] = vb.y;
            Bs[c4 + 2][row] = vb.z; Bs[c4 + 3][row] = vb.w;
        }
        __syncthreads();
#pragma unroll
        for (int kk = 0; kk < 16; kk++) {
            float a[8], b[8];
            *(float4*)&a[0] = *(const float4*)&As[kk][ty * 4];
            *(float4*)&a[4] = *(const float4*)&As[kk][64 + ty * 4];
            *(float4*)&b[0] = *(const float4*)&Bs[kk][tx * 4];
            *(float4*)&b[4] = *(const float4*)&Bs[kk][64 + tx * 4];
#pragma unroll
            for (int i = 0; i < 8; i++)
#pragma unroll
                for (int j = 0; j < 8; j++)
                    acc[i][j] = fmaf(a[i], b[j], acc[i][j]);
        }
        __syncthreads();
    }

#pragma unroll
    for (int mh = 0; mh < 2; mh++)
#pragma unroll
    for (int i = 0; i < 4; i++) {
        int m = m0 + mh * 64 + ty * 4 + i;
#pragma unroll
        for (int nh = 0; nh < 2; nh++) {
            int n = n0 + nh * 64 + tx * 4;
            float4 bv = *(const float4*)(bias + n);
            float4 o;
            o.x = (acc[mh * 4 + i][nh * 4 + 0] + bv.x) * scale;
            o.y = (acc[mh * 4 + i][nh * 4 + 1] + bv.y) * scale;
            o.z = (acc[mh * 4 + i][nh * 4 + 2] + bv.z) * scale;
            o.w = (acc[mh * 4 + i][nh * 4 + 3] + bv.w) * scale;
            int b_ = m >> 11, s_ = m & 2047;
            int h_ = n >> 6,  d_ = n & 63;
            *(float4*)(dst + (((b_ * NH + h_) * SS) + s_) * DH + d_) = o;
        }
    }
}

// Output GEMM: reads g_attn, writes external out pointer (row-major).
__global__ __launch_bounds__(256, 2) void gemm_out(
    const float* __restrict__ W, const float* __restrict__ bias,
    float* __restrict__ C)
{
    const float* A = g_attn;
    __shared__ __align__(16) float As[16][132];
    __shared__ __align__(16) float Bs[16][132];
    const int tid = threadIdx.x;
    const int tx = tid & 15, ty = tid >> 4;
    const int m0 = blockIdx.y * 128;
    const int n0 = blockIdx.x * 128;

    float acc[8][8];
#pragma unroll
    for (int i = 0; i < 8; i++)
#pragma unroll
        for (int j = 0; j < 8; j++) acc[i][j] = 0.f;

    for (int k0 = 0; k0 < 512; k0 += 16) {
#pragma unroll
        for (int r = 0; r < 2; r++) {
            int f = tid + r * 256;
            int row = f >> 2;
            int c4 = (f & 3) * 4;
            float4 va = *(const float4*)(A + (m0 + row) * 512 + k0 + c4);
            As[c4 + 0][row] = va.x; As[c4 + 1][row] = va.y;
            As[c4 + 2][row] = va.z; As[c4 + 3][row] = va.w;
            float4 vb = *(const float4*)(W + (n0 + row) * 512 + k0 + c4);
            Bs[c4 + 0][row] = vb.x; Bs[c4 + 1][row] = vb.y;
            Bs[c4 + 2][row] = vb.z; Bs[c4 + 3][row] = vb.w;
        }
        __syncthreads();
#pragma unroll
        for (int kk = 0; kk < 16; kk++) {
            float a[8], b[8];
            *(float4*)&a[0] = *(const float4*)&As[kk][ty * 4];
            *(float4*)&a[4] = *(const float4*)&As[kk][64 + ty * 4];
            *(float4*)&b[0] = *(const float4*)&Bs[kk][tx * 4];
            *(float4*)&b[4] = *(const float4*)&Bs[kk][64 + tx * 4];
#pragma unroll
            for (int i = 0; i < 8; i++)
#pragma unroll
                for (int j = 0; j < 8; j++)
                    acc[i][j] = fmaf(a[i], b[j], acc[i][j]);
        }
        __syncthreads();
    }

#pragma unroll
    for (int mh = 0; mh < 2; mh++)
#pragma unroll
    for (int i = 0; i < 4; i++) {
        int m = m0 + mh * 64 + ty * 4 + i;
#pragma unroll
        for (int nh = 0; nh < 2; nh++) {
            int n = n0 + nh * 64 + tx * 4;
            float4 bv = *(const float4*)(bias + n);
            float4 o;
            o.x = acc[mh * 4 + i][nh * 4 + 0] + bv.x;
            o.y = acc[mh * 4 + i][nh * 4 + 1] + bv.y;
            o.z = acc[mh * 4 + i][nh * 4 + 2] + bv.z;
            o.w = acc[mh * 4 + i][nh * 4 + 3] + bv.w;
            *(float4*)(C + m * 512 + n) = o;
        }
    }
}

// ---------------------------------------------------------------------------
extern "C" void kernel_launch(void* const* d_in, const int* in_sizes, int n_in,
                              void* d_out, int out_size)
{
    const float* q  = (const float*)d_in[0];
    const float* k  = (const float*)d_in[1];
    const float* v  = (const float*)d_in[2];
    const float* ab = (const float*)d_in[3];
    const float* Wq = (const float*)d_in[4];
    const float* bq = (const float*)d_in[5];
    const float* Wk = (const float*)d_in[6];
    const float* bk = (const float*)d_in[7];
    const float* Wv = (const float*)d_in[8];
    const float* bv = (const float*)d_in[9];
    const float* Wb = (const float*)d_in[10];
    const float* bbv = (const float*)d_in[11];
    const float* Wo = (const float*)d_in[12];
    const float* bo = (const float*)d_in[13];
    float* out = (float*)d_out;

    dim3 gg(4, 64);   // N tiles x M tiles
    gemm_proj_impl<<<gg, 256>>>(q, Wq, bq, 0, 0.125f);  // scale = DH^-0.5 folded into Q
    gemm_proj_impl<<<gg, 256>>>(k, Wk, bk, 1, 1.0f);
    gemm_proj_impl<<<gg, 256>>>(v, Wv, bv, 2, 1.0f);
    bias_kernel<<<65536, 256>>>(ab, Wb, bbv);
    attn_kernel<<<1024, 256>>>();
    gemm_out<<<gg, 256>>>(Wo, bo, out);
}

// round 4
// speedup vs baseline: 1.9572x; 1.9572x over previous
#include <cuda_runtime.h>
#include <cstdint>

#define BB 4
#define SS 2048
#define HIDD 512
#define NH 8
#define DH 64

// Scratch device globals (allocation-guard-safe), referenced directly by kernels.
__device__ float g_qh[BB*NH*SS*DH];            // 16 MB [b][h][s][d], q pre-scaled by 1/8
__device__ float g_kh[BB*NH*SS*DH];            // 16 MB
__device__ float g_vh[BB*NH*SS*DH];            // 16 MB
__device__ float g_attn[BB*SS*HIDD];           // 16 MB [b][s][h*64+d]
__device__ float g_biasH[(size_t)BB*NH*SS*SS]; // 537 MB [b][h][q][k]

// ---------------------------------------------------------------------------
// tf32 helpers
// ---------------------------------------------------------------------------
__device__ __forceinline__ unsigned f2tf(float x) {
    unsigned u; asm("cvt.rna.tf32.f32 %0, %1;" : "=r"(u) : "f"(x)); return u;
}
__device__ __forceinline__ void mma_tf32(float4& d,
    unsigned a0, unsigned a1, unsigned a2, unsigned a3,
    unsigned b0, unsigned b1)
{
    asm volatile("mma.sync.aligned.m16n8k8.row.col.f32.tf32.tf32.f32 "
        "{%0,%1,%2,%3}, {%4,%5,%6,%7}, {%8,%9}, {%0,%1,%2,%3};\n"
        : "+f"(d.x), "+f"(d.y), "+f"(d.z), "+f"(d.w)
        : "r"(a0), "r"(a1), "r"(a2), "r"(a3), "r"(b0), "r"(b1));
}

// ---------------------------------------------------------------------------
// tf32 GEMM (NT): C[m,n] = (sum_k A[m,k] * W[n,k] + bias[n]) * scale
// M=8192, N=K=512. CTA tile 128x128, 8 warps of 32x64, double-buffered k16.
// which: 0->g_qh, 1->g_kh, 2->g_vh (scatter [b][h][s][d]); 3: A=g_attn, C=Cout row-major.
// ---------------------------------------------------------------------------
__global__ __launch_bounds__(256, 2) void gemm_tf32(
    const float* __restrict__ Ain, const float* __restrict__ W,
    const float* __restrict__ bias, int which, float scale, float* __restrict__ Cout)
{
    const float* A = (which == 3) ? g_attn : Ain;

    __shared__ float As[2][128 * 20];
    __shared__ float Ws[2][128 * 20];

    const int tid = threadIdx.x;
    const int lane = tid & 31;
    const int wid = tid >> 5;
    const int wm = wid & 3;          // 0..3 -> 32 rows each
    const int wn = wid >> 2;         // 0..1 -> 64 cols each
    const int gid = lane >> 2;       // 0..7
    const int qid = lane & 3;        // 0..3
    const int m0 = blockIdx.y * 128;
    const int n0 = blockIdx.x * 128;

    float4 acc[2][8];
#pragma unroll
    for (int mt = 0; mt < 2; mt++)
#pragma unroll
        for (int nt = 0; nt < 8; nt++) acc[mt][nt] = make_float4(0.f, 0.f, 0.f, 0.f);

    // prologue: stage 0
#pragma unroll
    for (int r = 0; r < 2; r++) {
        int i = tid + r * 256;
        int row = i >> 2, c4 = (i & 3) * 4;
        float4 va = *(const float4*)(A + (size_t)(m0 + row) * 512 + c4);
        float4 ca;
        ca.x = __uint_as_float(f2tf(va.x)); ca.y = __uint_as_float(f2tf(va.y));
        ca.z = __uint_as_float(f2tf(va.z)); ca.w = __uint_as_float(f2tf(va.w));
        *(float4*)&As[0][row * 20 + c4] = ca;
        float4 vw = *(const float4*)(W + (size_t)(n0 + row) * 512 + c4);
        float4 cw;
        cw.x = __uint_as_float(f2tf(vw.x)); cw.y = __uint_as_float(f2tf(vw.y));
        cw.z = __uint_as_float(f2tf(vw.z)); cw.w = __uint_as_float(f2tf(vw.w));
        *(float4*)&Ws[0][row * 20 + c4] = cw;
    }
    __syncthreads();

    for (int s = 0; s < 32; s++) {
        const int buf = s & 1;
        float4 pa[2], pw[2];
        if (s < 31) {
            int k0 = (s + 1) * 16;
#pragma unroll
            for (int r = 0; r < 2; r++) {
                int i = tid + r * 256;
                int row = i >> 2, c4 = (i & 3) * 4;
                pa[r] = *(const float4*)(A + (size_t)(m0 + row) * 512 + k0 + c4);
                pw[r] = *(const float4*)(W + (size_t)(n0 + row) * 512 + k0 + c4);
            }
        }

#pragma unroll
        for (int kk = 0; kk < 2; kk++) {
            const int kb = kk * 8;
            unsigned a0[2], a1[2], a2[2], a3[2];
#pragma unroll
            for (int mt = 0; mt < 2; mt++) {
                int base = wm * 32 + mt * 16;
                a0[mt] = __float_as_uint(As[buf][(base + gid) * 20 + kb + qid]);
                a1[mt] = __float_as_uint(As[buf][(base + gid + 8) * 20 + kb + qid]);
                a2[mt] = __float_as_uint(As[buf][(base + gid) * 20 + kb + qid + 4]);
                a3[mt] = __float_as_uint(As[buf][(base + gid + 8) * 20 + kb + qid + 4]);
            }
#pragma unroll
            for (int nt = 0; nt < 8; nt++) {
                int nb = wn * 64 + nt * 8;
                unsigned b0 = __float_as_uint(Ws[buf][(nb + gid) * 20 + kb + qid]);
                unsigned b1 = __float_as_uint(Ws[buf][(nb + gid) * 20 + kb + qid + 4]);
                mma_tf32(acc[0][nt], a0[0], a1[0], a2[0], a3[0], b0, b1);
                mma_tf32(acc[1][nt], a0[1], a1[1], a2[1], a3[1], b0, b1);
            }
        }

        if (s < 31) {
            const int nb = buf ^ 1;
#pragma unroll
            for (int r = 0; r < 2; r++) {
                int i = tid + r * 256;
                int row = i >> 2, c4 = (i & 3) * 4;
                float4 ca;
                ca.x = __uint_as_float(f2tf(pa[r].x)); ca.y = __uint_as_float(f2tf(pa[r].y));
                ca.z = __uint_as_float(f2tf(pa[r].z)); ca.w = __uint_as_float(f2tf(pa[r].w));
                *(float4*)&As[nb][row * 20 + c4] = ca;
                float4 cw;
                cw.x = __uint_as_float(f2tf(pw[r].x)); cw.y = __uint_as_float(f2tf(pw[r].y));
                cw.z = __uint_as_float(f2tf(pw[r].z)); cw.w = __uint_as_float(f2tf(pw[r].w));
                *(float4*)&Ws[nb][row * 20 + c4] = cw;
            }
        }
        __syncthreads();
    }

    // epilogue
    float* dst = (which == 0) ? g_qh : (which == 1) ? g_kh : (which == 2) ? g_vh : Cout;
#pragma unroll
    for (int mt = 0; mt < 2; mt++) {
        int r_lo = m0 + wm * 32 + mt * 16 + gid;
        int r_hi = r_lo + 8;
#pragma unroll
        for (int nt = 0; nt < 8; nt++) {
            int n = n0 + wn * 64 + nt * 8 + qid * 2;
            float2 bv = *(const float2*)(bias + n);
            float2 o_lo, o_hi;
            o_lo.x = (acc[mt][nt].x + bv.x) * scale;
            o_lo.y = (acc[mt][nt].y + bv.y) * scale;
            o_hi.x = (acc[mt][nt].z + bv.x) * scale;
            o_hi.y = (acc[mt][nt].w + bv.y) * scale;
            if (which < 3) {
                int h_ = n >> 6, d_ = n & 63;
                int b_lo = r_lo >> 11, s_lo = r_lo & 2047;
                int b_hi = r_hi >> 11, s_hi = r_hi & 2047;
                *(float2*)(dst + (size_t)(((b_lo * NH + h_) * SS) + s_lo) * DH + d_) = o_lo;
                *(float2*)(dst + (size_t)(((b_hi * NH + h_) * SS) + s_hi) * DH + d_) = o_hi;
            } else {
                *(float2*)(dst + (size_t)r_lo * 512 + n) = o_lo;
                *(float2*)(dst + (size_t)r_hi * 512 + n) = o_hi;
            }
        }
    }
}

// ---------------------------------------------------------------------------
// Bias projection (unchanged; measured at DRAM roofline, 155us)
// ---------------------------------------------------------------------------
__global__ __launch_bounds__(256) void bias_kernel(
    const float* __restrict__ ab, const float* __restrict__ Wb,
    const float* __restrict__ bbv)
{
    __shared__ float wsh[64];
    __shared__ float bsh[8];
    if (threadIdx.x < 64) wsh[threadIdx.x] = Wb[threadIdx.x];
    if (threadIdx.x < 8)  bsh[threadIdx.x] = bbv[threadIdx.x];
    __syncthreads();

    int idx = blockIdx.x * 256 + threadIdx.x;
    float4 a0 = *(const float4*)(ab + (size_t)idx * 8);
    float4 a1 = *(const float4*)(ab + (size_t)idx * 8 + 4);
    int b_ = idx >> 22;
    int rem = idx & 4194303;
    int q_ = rem >> 11;
    int k_ = rem & 2047;

#pragma unroll
    for (int h = 0; h < 8; h++) {
        float v = bsh[h];
        v = fmaf(a0.x, wsh[h * 8 + 0], v);
        v = fmaf(a0.y, wsh[h * 8 + 1], v);
        v = fmaf(a0.z, wsh[h * 8 + 2], v);
        v = fmaf(a0.w, wsh[h * 8 + 3], v);
        v = fmaf(a1.x, wsh[h * 8 + 4], v);
        v = fmaf(a1.y, wsh[h * 8 + 5], v);
        v = fmaf(a1.z, wsh[h * 8 + 6], v);
        v = fmaf(a1.w, wsh[h * 8 + 7], v);
        g_biasH[(((size_t)(b_ * NH + h) * SS + q_) * SS) + k_] = v;
    }
}

// ---------------------------------------------------------------------------
// Flash attention with tf32 mma. CTA = 128 threads (4 warps), q-tile 64
// (16 rows/warp), k-tile 32. Q frags register-resident. Online softmax.
// ---------------------------------------------------------------------------
__global__ __launch_bounds__(128, 4) void attn_kernel()
{
    __shared__ float Ks[32 * 68];   // [k][d], pad 4 -> conflict-free 8x4 frag reads
    __shared__ float Vs[32 * 72];   // [k][d], pad 8 -> conflict-free 4x8 frag reads
    __shared__ float Ps[64 * 36];   // [q][k] tf32 bits, pad 4

    const int tid = threadIdx.x;
    const int lane = tid & 31;
    const int wq = tid >> 5;         // warp -> q rows [wq*16, wq*16+16)
    const int gid = lane >> 2;
    const int qid = lane & 3;
    const int qt = blockIdx.x & 31;
    const int bh = blockIdx.x >> 5;  // b*8 + h

    const float* qg = g_qh + (size_t)(bh * SS + qt * 64) * DH;
    const float* kg = g_kh + (size_t)bh * SS * DH;
    const float* vg = g_vh + (size_t)bh * SS * DH;
    const float* bg = g_biasH + (size_t)(bh * SS + qt * 64) * SS;

    // Q fragments (row-major A frags), once per CTA
    unsigned qa[8][4];
    {
        const float* q_lo = qg + (wq * 16 + gid) * DH;
        const float* q_hi = q_lo + 8 * DH;
#pragma unroll
        for (int dc = 0; dc < 8; dc++) {
            qa[dc][0] = f2tf(q_lo[dc * 8 + qid]);
            qa[dc][1] = f2tf(q_hi[dc * 8 + qid]);
            qa[dc][2] = f2tf(q_lo[dc * 8 + qid + 4]);
            qa[dc][3] = f2tf(q_hi[dc * 8 + qid + 4]);
        }
    }

    float4 O[8];
#pragma unroll
    for (int dt = 0; dt < 8; dt++) O[dt] = make_float4(0.f, 0.f, 0.f, 0.f);
    float m_lo = -1e30f, m_hi = -1e30f, l_lo = 0.f, l_hi = 0.f;

    for (int kt = 0; kt < 64; kt++) {
        __syncthreads();
        // stage K,V tiles (32x64 each), cvt to tf32
#pragma unroll
        for (int r = 0; r < 4; r++) {
            int i = tid + r * 128;
            int row = i >> 4, c4 = (i & 15) * 4;
            float4 kv = *(const float4*)(kg + (size_t)(kt * 32 + row) * DH + c4);
            float4 ck;
            ck.x = __uint_as_float(f2tf(kv.x)); ck.y = __uint_as_float(f2tf(kv.y));
            ck.z = __uint_as_float(f2tf(kv.z)); ck.w = __uint_as_float(f2tf(kv.w));
            *(float4*)&Ks[row * 68 + c4] = ck;
            float4 vv = *(const float4*)(vg + (size_t)(kt * 32 + row) * DH + c4);
            float4 cv;
            cv.x = __uint_as_float(f2tf(vv.x)); cv.y = __uint_as_float(f2tf(vv.y));
            cv.z = __uint_as_float(f2tf(vv.z)); cv.w = __uint_as_float(f2tf(vv.w));
            *(float4*)&Vs[row * 72 + c4] = cv;
        }
        __syncthreads();

        // S = Q K^T  (16 x 32 per warp)
        float4 S[4];
#pragma unroll
        for (int nt = 0; nt < 4; nt++) S[nt] = make_float4(0.f, 0.f, 0.f, 0.f);
#pragma unroll
        for (int dc = 0; dc < 8; dc++) {
#pragma unroll
            for (int nt = 0; nt < 4; nt++) {
                unsigned b0 = __float_as_uint(Ks[(nt * 8 + gid) * 68 + dc * 8 + qid]);
                unsigned b1 = __float_as_uint(Ks[(nt * 8 + gid) * 68 + dc * 8 + qid + 4]);
                mma_tf32(S[nt], qa[dc][0], qa[dc][1], qa[dc][2], qa[dc][3], b0, b1);
            }
        }

        // bias + running max
        const float* b_lo = bg + (size_t)(wq * 16 + gid) * SS + kt * 32 + qid * 2;
        const float* b_hi = b_lo + 8 * SS;
        float mn_lo = m_lo, mn_hi = m_hi;
#pragma unroll
        for (int nt = 0; nt < 4; nt++) {
            float2 blo = *(const float2*)(b_lo + nt * 8);
            float2 bhi = *(const float2*)(b_hi + nt * 8);
            S[nt].x += blo.x; S[nt].y += blo.y;
            S[nt].z += bhi.x; S[nt].w += bhi.y;
            mn_lo = fmaxf(mn_lo, fmaxf(S[nt].x, S[nt].y));
            mn_hi = fmaxf(mn_hi, fmaxf(S[nt].z, S[nt].w));
        }
        mn_lo = fmaxf(mn_lo, __shfl_xor_sync(0xffffffffu, mn_lo, 1));
        mn_lo = fmaxf(mn_lo, __shfl_xor_sync(0xffffffffu, mn_lo, 2));
        mn_hi = fmaxf(mn_hi, __shfl_xor_sync(0xffffffffu, mn_hi, 1));
        mn_hi = fmaxf(mn_hi, __shfl_xor_sync(0xffffffffu, mn_hi, 2));

        float fac_lo = __expf(m_lo - mn_lo);
        float fac_hi = __expf(m_hi - mn_hi);
        m_lo = mn_lo; m_hi = mn_hi;

        float rs_lo = 0.f, rs_hi = 0.f;
        float* p_lo = Ps + (wq * 16 + gid) * 36;
        float* p_hi = p_lo + 8 * 36;
#pragma unroll
        for (int nt = 0; nt < 4; nt++) {
            float p0 = __expf(S[nt].x - mn_lo);
            float p1 = __expf(S[nt].y - mn_lo);
            float p2 = __expf(S[nt].z - mn_hi);
            float p3 = __expf(S[nt].w - mn_hi);
            rs_lo += p0 + p1; rs_hi += p2 + p3;
            float2 st;
            st.x = __uint_as_float(f2tf(p0)); st.y = __uint_as_float(f2tf(p1));
            *(float2*)&p_lo[nt * 8 + qid * 2] = st;
            st.x = __uint_as_float(f2tf(p2)); st.y = __uint_as_float(f2tf(p3));
            *(float2*)&p_hi[nt * 8 + qid * 2] = st;
        }
        rs_lo += __shfl_xor_sync(0xffffffffu, rs_lo, 1);
        rs_lo += __shfl_xor_sync(0xffffffffu, rs_lo, 2);
        rs_hi += __shfl_xor_sync(0xffffffffu, rs_hi, 1);
        rs_hi += __shfl_xor_sync(0xffffffffu, rs_hi, 2);
        l_lo = l_lo * fac_lo + rs_lo;
        l_hi = l_hi * fac_hi + rs_hi;

#pragma unroll
        for (int dt = 0; dt < 8; dt++) {
            O[dt].x *= fac_lo; O[dt].y *= fac_lo;
            O[dt].z *= fac_hi; O[dt].w *= fac_hi;
        }
        __syncwarp();

        // O += P V   (A frags from Ps, B frags from Vs)
#pragma unroll
        for (int kc = 0; kc < 4; kc++) {
            unsigned a0 = __float_as_uint(p_lo[kc * 8 + qid]);
            unsigned a1 = __float_as_uint(p_hi[kc * 8 + qid]);
            unsigned a2 = __float_as_uint(p_lo[kc * 8 + qid + 4]);
            unsigned a3 = __float_as_uint(p_hi[kc * 8 + qid + 4]);
#pragma unroll
            for (int dt = 0; dt < 8; dt++) {
                unsigned b0 = __float_as_uint(Vs[(kc * 8 + qid) * 72 + dt * 8 + gid]);
                unsigned b1 = __float_as_uint(Vs[(kc * 8 + qid + 4) * 72 + dt * 8 + gid]);
                mma_tf32(O[dt], a0, a1, a2, a3, b0, b1);
            }
        }
    }

    // epilogue: normalize, write [b][s][h*64+d]
    const int b_ = bh >> 3, h_ = bh & 7;
    const float inv_lo = 1.f / l_lo;
    const float inv_hi = 1.f / l_hi;
    int row_lo = qt * 64 + wq * 16 + gid;
    float* o_lo = g_attn + (size_t)(b_ * SS + row_lo) * HIDD + h_ * 64;
    float* o_hi = o_lo + 8 * HIDD;
#pragma unroll
    for (int dt = 0; dt < 8; dt++) {
        float2 w;
        w.x = O[dt].x * inv_lo; w.y = O[dt].y * inv_lo;
        *(float2*)(o_lo + dt * 8 + qid * 2) = w;
        w.x = O[dt].z * inv_hi; w.y = O[dt].w * inv_hi;
        *(float2*)(o_hi + dt * 8 + qid * 2) = w;
    }
}

// ---------------------------------------------------------------------------
extern "C" void kernel_launch(void* const* d_in, const int* in_sizes, int n_in,
                              void* d_out, int out_size)
{
    const float* q   = (const float*)d_in[0];
    const float* k   = (const float*)d_in[1];
    const float* v   = (const float*)d_in[2];
    const float* ab  = (const float*)d_in[3];
    const float* Wq  = (const float*)d_in[4];
    const float* bq  = (const float*)d_in[5];
    const float* Wk  = (const float*)d_in[6];
    const float* bk  = (const float*)d_in[7];
    const float* Wv  = (const float*)d_in[8];
    const float* bv  = (const float*)d_in[9];
    const float* Wb  = (const float*)d_in[10];
    const float* bbv = (const float*)d_in[11];
    const float* Wo  = (const float*)d_in[12];
    const float* bo  = (const float*)d_in[13];
    float* out = (float*)d_out;

    dim3 gg(4, 64);   // n-tiles x m-tiles
    gemm_tf32<<<gg, 256>>>(q, Wq, bq, 0, 0.125f, nullptr);   // 1/sqrt(64) folded into Q
    gemm_tf32<<<gg, 256>>>(k, Wk, bk, 1, 1.0f, nullptr);
    gemm_tf32<<<gg, 256>>>(v, Wv, bv, 2, 1.0f, nullptr);
    bias_kernel<<<65536, 256>>>(ab, Wb, bbv);
    attn_kernel<<<1024, 128>>>();
    gemm_tf32<<<gg, 256>>>(nullptr, Wo, bo, 3, 1.0f, out);
}

// round 6
// speedup vs baseline: 2.5888x; 1.3227x over previous
#include <cuda_runtime.h>
#include <cuda_bf16.h>
#include <cstdint>

#define BB 4
#define SS 2048
#define HIDD 512
#define NH 8
#define DH 64

// Scratch device globals (allocation-guard-safe), referenced directly by kernels.
__device__ float g_qh[BB*NH*SS*DH];            // 16 MB [b][h][s][d], q pre-scaled by 1/8
__device__ float g_kh[BB*NH*SS*DH];            // 16 MB
__device__ float g_vh[BB*NH*SS*DH];            // 16 MB
__device__ float g_attn[BB*SS*HIDD];           // 16 MB [b][s][h*64+d]
__device__ __nv_bfloat16 g_biasB[(size_t)BB*NH*SS*SS]; // 268 MB bf16 [b][h][q][k]

// ---------------------------------------------------------------------------
// tf32 / cp.async helpers
// ---------------------------------------------------------------------------
__device__ __forceinline__ unsigned f2tf(float x) {
    unsigned u; asm("cvt.rna.tf32.f32 %0, %1;" : "=r"(u) : "f"(x)); return u;
}
__device__ __forceinline__ void mma_tf32(float4& d,
    unsigned a0, unsigned a1, unsigned a2, unsigned a3,
    unsigned b0, unsigned b1)
{
    asm volatile("mma.sync.aligned.m16n8k8.row.col.f32.tf32.tf32.f32 "
        "{%0,%1,%2,%3}, {%4,%5,%6,%7}, {%8,%9}, {%0,%1,%2,%3};\n"
        : "+f"(d.x), "+f"(d.y), "+f"(d.z), "+f"(d.w)
        : "r"(a0), "r"(a1), "r"(a2), "r"(a3), "r"(b0), "r"(b1));
}
__device__ __forceinline__ void cpa16(uint32_t s, const void* g) {
    asm volatile("cp.async.cg.shared.global [%0], [%1], 16;" :: "r"(s), "l"(g));
}
__device__ __forceinline__ void cpa_commit() {
    asm volatile("cp.async.commit_group;");
}
template<int N> __device__ __forceinline__ void cpa_wait() {
    asm volatile("cp.async.wait_group %0;" :: "n"(N));
}

// ---------------------------------------------------------------------------
// tf32 GEMM (NT): C[m,n] = (sum_k A[m,k] * W[n,k] + bias[n]) * scale
// M=8192, N=K=512. CTA tile 128x128, 8 warps of 32x64, double-buffered k16.
// which: 0->g_qh, 1->g_kh, 2->g_vh (scatter [b][h][s][d]); 3: A=g_attn, C=Cout.
// ---------------------------------------------------------------------------
__global__ __launch_bounds__(256, 2) void gemm_tf32(
    const float* __restrict__ Ain, const float* __restrict__ W,
    const float* __restrict__ bias, int which, float scale, float* __restrict__ Cout)
{
    const float* A = (which == 3) ? g_attn : Ain;

    __shared__ float As[2][128 * 20];
    __shared__ float Ws[2][128 * 20];

    const int tid = threadIdx.x;
    const int lane = tid & 31;
    const int wid = tid >> 5;
    const int wm = wid & 3;
    const int wn = wid >> 2;
    const int gid = lane >> 2;
    const int qid = lane & 3;
    const int m0 = blockIdx.y * 128;
    const int n0 = blockIdx.x * 128;

    float4 acc[2][8];
#pragma unroll
    for (int mt = 0; mt < 2; mt++)
#pragma unroll
        for (int nt = 0; nt < 8; nt++) acc[mt][nt] = make_float4(0.f, 0.f, 0.f, 0.f);

#pragma unroll
    for (int r = 0; r < 2; r++) {
        int i = tid + r * 256;
        int row = i >> 2, c4 = (i & 3) * 4;
        float4 va = *(const float4*)(A + (size_t)(m0 + row) * 512 + c4);
        float4 ca;
        ca.x = __uint_as_float(f2tf(va.x)); ca.y = __uint_as_float(f2tf(va.y));
        ca.z = __uint_as_float(f2tf(va.z)); ca.w = __uint_as_float(f2tf(va.w));
        *(float4*)&As[0][row * 20 + c4] = ca;
        float4 vw = *(const float4*)(W + (size_t)(n0 + row) * 512 + c4);
        float4 cw;
        cw.x = __uint_as_float(f2tf(vw.x)); cw.y = __uint_as_float(f2tf(vw.y));
        cw.z = __uint_as_float(f2tf(vw.z)); cw.w = __uint_as_float(f2tf(vw.w));
        *(float4*)&Ws[0][row * 20 + c4] = cw;
    }
    __syncthreads();

    for (int s = 0; s < 32; s++) {
        const int buf = s & 1;
        float4 pa[2], pw[2];
        if (s < 31) {
            int k0 = (s + 1) * 16;
#pragma unroll
            for (int r = 0; r < 2; r++) {
                int i = tid + r * 256;
                int row = i >> 2, c4 = (i & 3) * 4;
                pa[r] = *(const float4*)(A + (size_t)(m0 + row) * 512 + k0 + c4);
                pw[r] = *(const float4*)(W + (size_t)(n0 + row) * 512 + k0 + c4);
            }
        }

#pragma unroll
        for (int kk = 0; kk < 2; kk++) {
            const int kb = kk * 8;
            unsigned a0[2], a1[2], a2[2], a3[2];
#pragma unroll
            for (int mt = 0; mt < 2; mt++) {
                int base = wm * 32 + mt * 16;
                a0[mt] = __float_as_uint(As[buf][(base + gid) * 20 + kb + qid]);
                a1[mt] = __float_as_uint(As[buf][(base + gid + 8) * 20 + kb + qid]);
                a2[mt] = __float_as_uint(As[buf][(base + gid) * 20 + kb + qid + 4]);
                a3[mt] = __float_as_uint(As[buf][(base + gid + 8) * 20 + kb + qid + 4]);
            }
#pragma unroll
            for (int nt = 0; nt < 8; nt++) {
                int nb = wn * 64 + nt * 8;
                unsigned b0 = __float_as_uint(Ws[buf][(nb + gid) * 20 + kb + qid]);
                unsigned b1 = __float_as_uint(Ws[buf][(nb + gid) * 20 + kb + qid + 4]);
                mma_tf32(acc[0][nt], a0[0], a1[0], a2[0], a3[0], b0, b1);
                mma_tf32(acc[1][nt], a0[1], a1[1], a2[1], a3[1], b0, b1);
            }
        }

        if (s < 31) {
            const int nb = buf ^ 1;
#pragma unroll
            for (int r = 0; r < 2; r++) {
                int i = tid + r * 256;
                int row = i >> 2, c4 = (i & 3) * 4;
                float4 ca;
                ca.x = __uint_as_float(f2tf(pa[r].x)); ca.y = __uint_as_float(f2tf(pa[r].y));
                ca.z = __uint_as_float(f2tf(pa[r].z)); ca.w = __uint_as_float(f2tf(pa[r].w));
                *(float4*)&As[nb][row * 20 + c4] = ca;
                float4 cw;
                cw.x = __uint_as_float(f2tf(pw[r].x)); cw.y = __uint_as_float(f2tf(pw[r].y));
                cw.z = __uint_as_float(f2tf(pw[r].z)); cw.w = __uint_as_float(f2tf(pw[r].w));
                *(float4*)&Ws[nb][row * 20 + c4] = cw;
            }
        }
        __syncthreads();
    }

    float* dst = (which == 0) ? g_qh : (which == 1) ? g_kh : (which == 2) ? g_vh : Cout;
#pragma unroll
    for (int mt = 0; mt < 2; mt++) {
        int r_lo = m0 + wm * 32 + mt * 16 + gid;
        int r_hi = r_lo + 8;
#pragma unroll
        for (int nt = 0; nt < 8; nt++) {
            int n = n0 + wn * 64 + nt * 8 + qid * 2;
            float2 bv = *(const float2*)(bias + n);
            float2 o_lo, o_hi;
            o_lo.x = (acc[mt][nt].x + bv.x) * scale;
            o_lo.y = (acc[mt][nt].y + bv.y) * scale;
            o_hi.x = (acc[mt][nt].z + bv.x) * scale;
            o_hi.y = (acc[mt][nt].w + bv.y) * scale;
            if (which < 3) {
                int h_ = n >> 6, d_ = n & 63;
                int b_lo = r_lo >> 11, s_lo = r_lo & 2047;
                int b_hi = r_hi >> 11, s_hi = r_hi & 2047;
                *(float2*)(dst + (size_t)(((b_lo * NH + h_) * SS) + s_lo) * DH + d_) = o_lo;
                *(float2*)(dst + (size_t)(((b_hi * NH + h_) * SS) + s_hi) * DH + d_) = o_hi;
            } else {
                *(float2*)(dst + (size_t)r_lo * 512 + n) = o_lo;
                *(float2*)(dst + (size_t)r_hi * 512 + n) = o_hi;
            }
        }
    }
}

// ---------------------------------------------------------------------------
// Bias projection -> bf16. Traffic: 537 MB read + 268 MB write.
// ---------------------------------------------------------------------------
__global__ __launch_bounds__(256) void bias_kernel(
    const float* __restrict__ ab, const float* __restrict__ Wb,
    const float* __restrict__ bbv)
{
    __shared__ float wsh[64];
    __shared__ float bsh[8];
    if (threadIdx.x < 64) wsh[threadIdx.x] = Wb[threadIdx.x];
    if (threadIdx.x < 8)  bsh[threadIdx.x] = bbv[threadIdx.x];
    __syncthreads();

    int idx = blockIdx.x * 256 + threadIdx.x;
    float4 a0 = *(const float4*)(ab + (size_t)idx * 8);
    float4 a1 = *(const float4*)(ab + (size_t)idx * 8 + 4);
    int b_ = idx >> 22;
    int rem = idx & 4194303;
    int q_ = rem >> 11;
    int k_ = rem & 2047;

#pragma unroll
    for (int h = 0; h < 8; h++) {
        float v = bsh[h];
        v = fmaf(a0.x, wsh[h * 8 + 0], v);
        v = fmaf(a0.y, wsh[h * 8 + 1], v);
        v = fmaf(a0.z, wsh[h * 8 + 2], v);
        v = fmaf(a0.w, wsh[h * 8 + 3], v);
        v = fmaf(a1.x, wsh[h * 8 + 4], v);
        v = fmaf(a1.y, wsh[h * 8 + 5], v);
        v = fmaf(a1.z, wsh[h * 8 + 6], v);
        v = fmaf(a1.w, wsh[h * 8 + 7], v);
        g_biasB[(((size_t)(b_ * NH + h) * SS + q_) * SS) + k_] = __float2bfloat16(v);
    }
}

// ---------------------------------------------------------------------------
// Flash attention, tf32 mma, cp.async double-buffered K/V (raw fp32 in smem,
// cvt at frag-load). CTA = 4 warps, q-tile 64 (16 rows/warp), k-tile 32.
// ---------------------------------------------------------------------------
__global__ __launch_bounds__(128) void attn_kernel()
{
    __shared__ float Ks[2][32 * 68];   // [k][d] pad 4
    __shared__ float Vs[2][32 * 72];   // [k][d] pad 8
    __shared__ float Ps[64 * 36];      // [q][k] tf32 bits, pad 4 (warp-private rows)

    const int tid = threadIdx.x;
    const int lane = tid & 31;
    const int wq = tid >> 5;
    const int gid = lane >> 2;
    const int qid = lane & 3;
    const int qt = blockIdx.x & 31;
    const int bh = blockIdx.x >> 5;

    const float* qg = g_qh + (size_t)(bh * SS + qt * 64) * DH;
    const float* kg = g_kh + (size_t)bh * SS * DH;
    const float* vg = g_vh + (size_t)bh * SS * DH;
    const __nv_bfloat16* bg = g_biasB + (size_t)(bh * SS + qt * 64) * SS;

    // per-thread staging addresses (4 chunks of 16B per tensor per tile)
    const int srow = tid >> 4;              // 0..7  (+8*r)
    const int sc4 = (tid & 15) * 4;         // 0..60
    uint32_t ks_base = (uint32_t)__cvta_generic_to_shared(&Ks[0][0]);
    uint32_t vs_base = (uint32_t)__cvta_generic_to_shared(&Vs[0][0]);

    // Q fragments, register-resident
    unsigned qa[8][4];
    {
        const float* q_lo = qg + (wq * 16 + gid) * DH;
        const float* q_hi = q_lo + 8 * DH;
#pragma unroll
        for (int dc = 0; dc < 8; dc++) {
            qa[dc][0] = f2tf(q_lo[dc * 8 + qid]);
            qa[dc][1] = f2tf(q_hi[dc * 8 + qid]);
            qa[dc][2] = f2tf(q_lo[dc * 8 + qid + 4]);
            qa[dc][3] = f2tf(q_hi[dc * 8 + qid + 4]);
        }
    }

    float4 O[8];
#pragma unroll
    for (int dt = 0; dt < 8; dt++) O[dt] = make_float4(0.f, 0.f, 0.f, 0.f);
    float m_lo = -1e30f, m_hi = -1e30f, l_lo = 0.f, l_hi = 0.f;

    // stage tile 0
#pragma unroll
    for (int r = 0; r < 4; r++) {
        int row = srow + r * 8;
        cpa16(ks_base + (row * 68 + sc4) * 4, kg + (size_t)row * DH + sc4);
        cpa16(vs_base + (row * 72 + sc4) * 4, vg + (size_t)row * DH + sc4);
    }
    cpa_commit();

    for (int kt = 0; kt < 64; kt++) {
        const int buf = kt & 1;
        if (kt < 63) {
            const int nb = buf ^ 1;
#pragma unroll
            for (int r = 0; r < 4; r++) {
                int row = srow + r * 8;
                cpa16(ks_base + (nb * 32 * 68 + row * 68 + sc4) * 4,
                      kg + (size_t)((kt + 1) * 32 + row) * DH + sc4);
                cpa16(vs_base + (nb * 32 * 72 + row * 72 + sc4) * 4,
                      vg + (size_t)((kt + 1) * 32 + row) * DH + sc4);
            }
            cpa_commit();
            cpa_wait<1>();
        } else {
            cpa_wait<0>();
        }
        __syncthreads();

        const float* ksb = &Ks[buf][0];
        const float* vsb = &Vs[buf][0];

        // S = Q K^T
        float4 S[4];
#pragma unroll
        for (int nt = 0; nt < 4; nt++) S[nt] = make_float4(0.f, 0.f, 0.f, 0.f);
#pragma unroll
        for (int dc = 0; dc < 8; dc++) {
#pragma unroll
            for (int nt = 0; nt < 4; nt++) {
                unsigned b0 = f2tf(ksb[(nt * 8 + gid) * 68 + dc * 8 + qid]);
                unsigned b1 = f2tf(ksb[(nt * 8 + gid) * 68 + dc * 8 + qid + 4]);
                mma_tf32(S[nt], qa[dc][0], qa[dc][1], qa[dc][2], qa[dc][3], b0, b1);
            }
        }

        // bias (bf16) + running max
        const __nv_bfloat16* b_lo = bg + (size_t)(wq * 16 + gid) * SS + kt * 32 + qid * 2;
        const __nv_bfloat16* b_hi = b_lo + 8 * SS;
        float mn_lo = m_lo, mn_hi = m_hi;
#pragma unroll
        for (int nt = 0; nt < 4; nt++) {
            float2 blo = __bfloat1622float2(*(const __nv_bfloat162*)(b_lo + nt * 8));
            float2 bhi = __bfloat1622float2(*(const __nv_bfloat162*)(b_hi + nt * 8));
            S[nt].x += blo.x; S[nt].y += blo.y;
            S[nt].z += bhi.x; S[nt].w += bhi.y;
            mn_lo = fmaxf(mn_lo, fmaxf(S[nt].x, S[nt].y));
            mn_hi = fmaxf(mn_hi, fmaxf(S[nt].z, S[nt].w));
        }
        mn_lo = fmaxf(mn_lo, __shfl_xor_sync(0xffffffffu, mn_lo, 1));
        mn_lo = fmaxf(mn_lo, __shfl_xor_sync(0xffffffffu, mn_lo, 2));
        mn_hi = fmaxf(mn_hi, __shfl_xor_sync(0xffffffffu, mn_hi, 1));
        mn_hi = fmaxf(mn_hi, __shfl_xor_sync(0xffffffffu, mn_hi, 2));

        float fac_lo = __expf(m_lo - mn_lo);
        float fac_hi = __expf(m_hi - mn_hi);
        m_lo = mn_lo; m_hi = mn_hi;

        float rs_lo = 0.f, rs_hi = 0.f;
        float* p_lo = Ps + (wq * 16 + gid) * 36;
        float* p_hi = p_lo + 8 * 36;
#pragma unroll
        for (int nt = 0; nt < 4; nt++) {
            float p0 = __expf(S[nt].x - mn_lo);
            float p1 = __expf(S[nt].y - mn_lo);
            float p2 = __expf(S[nt].z - mn_hi);
            float p3 = __expf(S[nt].w - mn_hi);
            rs_lo += p0 + p1; rs_hi += p2 + p3;
            float2 st;
            st.x = __uint_as_float(f2tf(p0)); st.y = __uint_as_float(f2tf(p1));
            *(float2*)&p_lo[nt * 8 + qid * 2] = st;
            st.x = __uint_as_float(f2tf(p2)); st.y = __uint_as_float(f2tf(p3));
            *(float2*)&p_hi[nt * 8 + qid * 2] = st;
        }
        rs_lo += __shfl_xor_sync(0xffffffffu, rs_lo, 1);
        rs_lo += __shfl_xor_sync(0xffffffffu, rs_lo, 2);
        rs_hi += __shfl_xor_sync(0xffffffffu, rs_hi, 1);
        rs_hi += __shfl_xor_sync(0xffffffffu, rs_hi, 2);
        l_lo = l_lo * fac_lo + rs_lo;
        l_hi = l_hi * fac_hi + rs_hi;

#pragma unroll
        for (int dt = 0; dt < 8; dt++) {
            O[dt].x *= fac_lo; O[dt].y *= fac_lo;
            O[dt].z *= fac_hi; O[dt].w *= fac_hi;
        }
        __syncwarp();

        // O += P V
#pragma unroll
        for (int kc = 0; kc < 4; kc++) {
            unsigned a0 = __float_as_uint(p_lo[kc * 8 + qid]);
            unsigned a1 = __float_as_uint(p_hi[kc * 8 + qid]);
            unsigned a2 = __float_as_uint(p_lo[kc * 8 + qid + 4]);
            unsigned a3 = __float_as_uint(p_hi[kc * 8 + qid + 4]);
#pragma unroll
            for (int dt = 0; dt < 8; dt++) {
                unsigned b0 = f2tf(vsb[(kc * 8 + qid) * 72 + dt * 8 + gid]);
                unsigned b1 = f2tf(vsb[(kc * 8 + qid + 4) * 72 + dt * 8 + gid]);
                mma_tf32(O[dt], a0, a1, a2, a3, b0, b1);
            }
        }
        __syncthreads();
    }

    // epilogue
    const int b_ = bh >> 3, h_ = bh & 7;
    const float inv_lo = 1.f / l_lo;
    const float inv_hi = 1.f / l_hi;
    int row_lo = qt * 64 + wq * 16 + gid;
    float* o_lo = g_attn + (size_t)(b_ * SS + row_lo) * HIDD + h_ * 64;
    float* o_hi = o_lo + 8 * HIDD;
#pragma unroll
    for (int dt = 0; dt < 8; dt++) {
        float2 w;
        w.x = O[dt].x * inv_lo; w.y = O[dt].y * inv_lo;
        *(float2*)(o_lo + dt * 8 + qid * 2) = w;
        w.x = O[dt].z * inv_hi; w.y = O[dt].w * inv_hi;
        *(float2*)(o_hi + dt * 8 + qid * 2) = w;
    }
}

// ---------------------------------------------------------------------------
extern "C" void kernel_launch(void* const* d_in, const int* in_sizes, int n_in,
                              void* d_out, int out_size)
{
    const float* q   = (const float*)d_in[0];
    const float* k   = (const float*)d_in[1];
    const float* v   = (const float*)d_in[2];
    const float* ab  = (const float*)d_in[3];
    const float* Wq  = (const float*)d_in[4];
    const float* bq  = (const float*)d_in[5];
    const float* Wk  = (const float*)d_in[6];
    const float* bk  = (const float*)d_in[7];
    const float* Wv  = (const float*)d_in[8];
    const float* bv  = (const float*)d_in[9];
    const float* Wb  = (const float*)d_in[10];
    const float* bbv = (const float*)d_in[11];
    const float* Wo  = (const float*)d_in[12];
    const float* bo  = (const float*)d_in[13];
    float* out = (float*)d_out;

    dim3 gg(4, 64);
    gemm_tf32<<<gg, 256>>>(q, Wq, bq, 0, 0.125f, nullptr);
    gemm_tf32<<<gg, 256>>>(k, Wk, bk, 1, 1.0f, nullptr);
    gemm_tf32<<<gg, 256>>>(v, Wv, bv, 2, 1.0f, nullptr);
    bias_kernel<<<65536, 256>>>(ab, Wb, bbv);
    attn_kernel<<<1024, 128>>>();
    gemm_tf32<<<gg, 256>>>(nullptr, Wo, bo, 3, 1.0f, out);
}

// round 7
// speedup vs baseline: 2.7188x; 1.0503x over previous
#include <cuda_runtime.h>
#include <cuda_bf16.h>
#include <cstdint>

#define BB 4
#define SS 2048
#define HIDD 512
#define NH 8
#define DH 64

__device__ float g_qh[BB*NH*SS*DH];            // [b][h][s][d], q pre-scaled by 1/8
__device__ float g_kh[BB*NH*SS*DH];
__device__ float g_vh[BB*NH*SS*DH];
__device__ float g_attn[BB*SS*HIDD];           // [b][s][h*64+d]
__device__ __nv_bfloat16 g_biasB[(size_t)BB*NH*SS*SS]; // 268 MB bf16 [b][h][q][k]

// ---------------------------------------------------------------------------
__device__ __forceinline__ unsigned f2tf(float x) {
    unsigned u; asm("cvt.rna.tf32.f32 %0, %1;" : "=r"(u) : "f"(x)); return u;
}
__device__ __forceinline__ void mma_tf32(float4& d,
    unsigned a0, unsigned a1, unsigned a2, unsigned a3,
    unsigned b0, unsigned b1)
{
    asm volatile("mma.sync.aligned.m16n8k8.row.col.f32.tf32.tf32.f32 "
        "{%0,%1,%2,%3}, {%4,%5,%6,%7}, {%8,%9}, {%0,%1,%2,%3};\n"
        : "+f"(d.x), "+f"(d.y), "+f"(d.z), "+f"(d.w)
        : "r"(a0), "r"(a1), "r"(a2), "r"(a3), "r"(b0), "r"(b1));
}
__device__ __forceinline__ void cpa16(uint32_t s, const void* g) {
    asm volatile("cp.async.cg.shared.global [%0], [%1], 16;" :: "r"(s), "l"(g));
}
__device__ __forceinline__ void cpa_commit() {
    asm volatile("cp.async.commit_group;");
}
template<int N> __device__ __forceinline__ void cpa_wait() {
    asm volatile("cp.async.wait_group %0;" :: "n"(N));
}

// ---------------------------------------------------------------------------
// GEMM core (NT), tf32: acc = A[128xK] * W[128xK]^T over K=512, tiles k16,
// double-buffered. Shared by qkv-fused and output GEMMs.
// ---------------------------------------------------------------------------
struct GemmOut { float4 acc[2][8]; };

__device__ __forceinline__ void gemm_core(
    const float* __restrict__ A, const float* __restrict__ W,
    int m0, int n0, float As[2][128*20], float Ws[2][128*20], GemmOut& G)
{
    const int tid = threadIdx.x;
    const int lane = tid & 31;
    const int wid = tid >> 5;
    const int wm = wid & 3;
    const int wn = wid >> 2;
    const int gid = lane >> 2;
    const int qid = lane & 3;

#pragma unroll
    for (int mt = 0; mt < 2; mt++)
#pragma unroll
        for (int nt = 0; nt < 8; nt++) G.acc[mt][nt] = make_float4(0.f, 0.f, 0.f, 0.f);

#pragma unroll
    for (int r = 0; r < 2; r++) {
        int i = tid + r * 256;
        int row = i >> 2, c4 = (i & 3) * 4;
        float4 va = *(const float4*)(A + (size_t)(m0 + row) * 512 + c4);
        float4 ca;
        ca.x = __uint_as_float(f2tf(va.x)); ca.y = __uint_as_float(f2tf(va.y));
        ca.z = __uint_as_float(f2tf(va.z)); ca.w = __uint_as_float(f2tf(va.w));
        *(float4*)&As[0][row * 20 + c4] = ca;
        float4 vw = *(const float4*)(W + (size_t)(n0 + row) * 512 + c4);
        float4 cw;
        cw.x = __uint_as_float(f2tf(vw.x)); cw.y = __uint_as_float(f2tf(vw.y));
        cw.z = __uint_as_float(f2tf(vw.z)); cw.w = __uint_as_float(f2tf(vw.w));
        *(float4*)&Ws[0][row * 20 + c4] = cw;
    }
    __syncthreads();

    for (int s = 0; s < 32; s++) {
        const int buf = s & 1;
        float4 pa[2], pw[2];
        if (s < 31) {
            int k0 = (s + 1) * 16;
#pragma unroll
            for (int r = 0; r < 2; r++) {
                int i = tid + r * 256;
                int row = i >> 2, c4 = (i & 3) * 4;
                pa[r] = *(const float4*)(A + (size_t)(m0 + row) * 512 + k0 + c4);
                pw[r] = *(const float4*)(W + (size_t)(n0 + row) * 512 + k0 + c4);
            }
        }
#pragma unroll
        for (int kk = 0; kk < 2; kk++) {
            const int kb = kk * 8;
            unsigned a0[2], a1[2], a2[2], a3[2];
#pragma unroll
            for (int mt = 0; mt < 2; mt++) {
                int base = wm * 32 + mt * 16;
                a0[mt] = __float_as_uint(As[buf][(base + gid) * 20 + kb + qid]);
                a1[mt] = __float_as_uint(As[buf][(base + gid + 8) * 20 + kb + qid]);
                a2[mt] = __float_as_uint(As[buf][(base + gid) * 20 + kb + qid + 4]);
                a3[mt] = __float_as_uint(As[buf][(base + gid + 8) * 20 + kb + qid + 4]);
            }
#pragma unroll
            for (int nt = 0; nt < 8; nt++) {
                int nb = wn * 64 + nt * 8;
                unsigned b0 = __float_as_uint(Ws[buf][(nb + gid) * 20 + kb + qid]);
                unsigned b1 = __float_as_uint(Ws[buf][(nb + gid) * 20 + kb + qid + 4]);
                mma_tf32(G.acc[0][nt], a0[0], a1[0], a2[0], a3[0], b0, b1);
                mma_tf32(G.acc[1][nt], a0[1], a1[1], a2[1], a3[1], b0, b1);
            }
        }
        if (s < 31) {
            const int nb = buf ^ 1;
#pragma unroll
            for (int r = 0; r < 2; r++) {
                int i = tid + r * 256;
                int row = i >> 2, c4 = (i & 3) * 4;
                float4 ca;
                ca.x = __uint_as_float(f2tf(pa[r].x)); ca.y = __uint_as_float(f2tf(pa[r].y));
                ca.z = __uint_as_float(f2tf(pa[r].z)); ca.w = __uint_as_float(f2tf(pa[r].w));
                *(float4*)&As[nb][row * 20 + c4] = ca;
                float4 cw;
                cw.x = __uint_as_float(f2tf(pw[r].x)); cw.y = __uint_as_float(f2tf(pw[r].y));
                cw.z = __uint_as_float(f2tf(pw[r].z)); cw.w = __uint_as_float(f2tf(pw[r].w));
                *(float4*)&Ws[nb][row * 20 + c4] = cw;
            }
        }
        __syncthreads();
    }
}

// Fused Q/K/V projections: blockIdx.z selects input/weight/bias/dst/scale.
__global__ __launch_bounds__(256, 2) void gemm_qkv(
    const float* __restrict__ q, const float* __restrict__ Wq, const float* __restrict__ bq,
    const float* __restrict__ k, const float* __restrict__ Wk, const float* __restrict__ bk,
    const float* __restrict__ v, const float* __restrict__ Wv, const float* __restrict__ bv)
{
    __shared__ float As[2][128 * 20];
    __shared__ float Ws[2][128 * 20];
    const int z = blockIdx.z;
    const float* A = (z == 0) ? q : (z == 1) ? k : v;
    const float* W = (z == 0) ? Wq : (z == 1) ? Wk : Wv;
    const float* bias = (z == 0) ? bq : (z == 1) ? bk : bv;
    float* dst = (z == 0) ? g_qh : (z == 1) ? g_kh : g_vh;
    const float scale = (z == 0) ? 0.125f : 1.0f;

    const int m0 = blockIdx.y * 128;
    const int n0 = blockIdx.x * 128;
    GemmOut G;
    gemm_core(A, W, m0, n0, As, Ws, G);

    const int lane = threadIdx.x & 31;
    const int wid = threadIdx.x >> 5;
    const int wm = wid & 3, wn = wid >> 2;
    const int gid = lane >> 2, qid = lane & 3;
#pragma unroll
    for (int mt = 0; mt < 2; mt++) {
        int r_lo = m0 + wm * 32 + mt * 16 + gid;
        int r_hi = r_lo + 8;
#pragma unroll
        for (int nt = 0; nt < 8; nt++) {
            int n = n0 + wn * 64 + nt * 8 + qid * 2;
            float2 bv2 = *(const float2*)(bias + n);
            float2 o_lo, o_hi;
            o_lo.x = (G.acc[mt][nt].x + bv2.x) * scale;
            o_lo.y = (G.acc[mt][nt].y + bv2.y) * scale;
            o_hi.x = (G.acc[mt][nt].z + bv2.x) * scale;
            o_hi.y = (G.acc[mt][nt].w + bv2.y) * scale;
            int h_ = n >> 6, d_ = n & 63;
            int b_lo = r_lo >> 11, s_lo = r_lo & 2047;
            int b_hi = r_hi >> 11, s_hi = r_hi & 2047;
            *(float2*)(dst + (size_t)(((b_lo * NH + h_) * SS) + s_lo) * DH + d_) = o_lo;
            *(float2*)(dst + (size_t)(((b_hi * NH + h_) * SS) + s_hi) * DH + d_) = o_hi;
        }
    }
}

// Output GEMM: A = g_attn, C row-major.
__global__ __launch_bounds__(256, 2) void gemm_out(
    const float* __restrict__ W, const float* __restrict__ bias, float* __restrict__ C)
{
    __shared__ float As[2][128 * 20];
    __shared__ float Ws[2][128 * 20];
    const int m0 = blockIdx.y * 128;
    const int n0 = blockIdx.x * 128;
    GemmOut G;
    gemm_core(g_attn, W, m0, n0, As, Ws, G);

    const int lane = threadIdx.x & 31;
    const int wid = threadIdx.x >> 5;
    const int wm = wid & 3, wn = wid >> 2;
    const int gid = lane >> 2, qid = lane & 3;
#pragma unroll
    for (int mt = 0; mt < 2; mt++) {
        int r_lo = m0 + wm * 32 + mt * 16 + gid;
        int r_hi = r_lo + 8;
#pragma unroll
        for (int nt = 0; nt < 8; nt++) {
            int n = n0 + wn * 64 + nt * 8 + qid * 2;
            float2 bv2 = *(const float2*)(bias + n);
            float2 o_lo, o_hi;
            o_lo.x = G.acc[mt][nt].x + bv2.x;
            o_lo.y = G.acc[mt][nt].y + bv2.y;
            o_hi.x = G.acc[mt][nt].z + bv2.x;
            o_hi.y = G.acc[mt][nt].w + bv2.y;
            *(float2*)(C + (size_t)r_lo * 512 + n) = o_lo;
            *(float2*)(C + (size_t)r_hi * 512 + n) = o_hi;
        }
    }
}

// ---------------------------------------------------------------------------
// Bias projection -> bf16 (measured at DRAM roofline).
// ---------------------------------------------------------------------------
__global__ __launch_bounds__(256) void bias_kernel(
    const float* __restrict__ ab, const float* __restrict__ Wb,
    const float* __restrict__ bbv)
{
    __shared__ float wsh[64];
    __shared__ float bsh[8];
    if (threadIdx.x < 64) wsh[threadIdx.x] = Wb[threadIdx.x];
    if (threadIdx.x < 8)  bsh[threadIdx.x] = bbv[threadIdx.x];
    __syncthreads();

    int idx = blockIdx.x * 256 + threadIdx.x;
    float4 a0 = *(const float4*)(ab + (size_t)idx * 8);
    float4 a1 = *(const float4*)(ab + (size_t)idx * 8 + 4);
    int b_ = idx >> 22;
    int rem = idx & 4194303;
    int q_ = rem >> 11;
    int k_ = rem & 2047;

#pragma unroll
    for (int h = 0; h < 8; h++) {
        float v = bsh[h];
        v = fmaf(a0.x, wsh[h * 8 + 0], v);
        v = fmaf(a0.y, wsh[h * 8 + 1], v);
        v = fmaf(a0.z, wsh[h * 8 + 2], v);
        v = fmaf(a0.w, wsh[h * 8 + 3], v);
        v = fmaf(a1.x, wsh[h * 8 + 4], v);
        v = fmaf(a1.y, wsh[h * 8 + 5], v);
        v = fmaf(a1.z, wsh[h * 8 + 6], v);
        v = fmaf(a1.w, wsh[h * 8 + 7], v);
        g_biasB[(((size_t)(b_ * NH + h) * SS + q_) * SS) + k_] = __float2bfloat16(v);
    }
}

// ---------------------------------------------------------------------------
// Flash attention: 4 warps, q-tile 128 (32 rows/warp = two m16 frags),
// k-tile 32. K double-buffered cp.async; V single-buffered via split commit
// groups (V(kt) load overlaps S-mma+softmax of iteration kt). B-frags shared
// across the two m-frags -> LDS+cvt per mma halved vs q16/warp.
// ---------------------------------------------------------------------------
__global__ __launch_bounds__(128, 2) void attn_kernel()
{
    __shared__ float Ks[2][32 * 68];   // 17408 B
    __shared__ float Vs[32 * 72];      //  9216 B
    __shared__ float Ps[128 * 36];     // 18432 B  (44 KB total)

    const int tid = threadIdx.x;
    const int lane = tid & 31;
    const int wq = tid >> 5;
    const int gid = lane >> 2;
    const int qid = lane & 3;
    const int qt = blockIdx.x & 15;        // 16 q-tiles of 128
    const int bh = blockIdx.x >> 4;        // b*8 + h
    const int r0 = wq * 32;                // warp's q-row base within tile

    const float* qg = g_qh + (size_t)(bh * SS + qt * 128) * DH;
    const float* kg = g_kh + (size_t)bh * SS * DH;
    const float* vg = g_vh + (size_t)bh * SS * DH;
    const __nv_bfloat16* bg = g_biasB + (size_t)(bh * SS + qt * 128) * SS;

    const int srow = tid >> 4;             // 0..7 (+8*r)
    const int sc4 = (tid & 15) * 4;        // 0..60
    uint32_t ks_base = (uint32_t)__cvta_generic_to_shared(&Ks[0][0]);
    uint32_t vs_base = (uint32_t)__cvta_generic_to_shared(&Vs[0]);

    // Q fragments: two m16 frags per warp, register-resident
    unsigned qa[8][2][4];
#pragma unroll
    for (int f = 0; f < 2; f++) {
        const float* q_lo = qg + (r0 + f * 16 + gid) * DH;
        const float* q_hi = q_lo + 8 * DH;
#pragma unroll
        for (int dc = 0; dc < 8; dc++) {
            qa[dc][f][0] = f2tf(q_lo[dc * 8 + qid]);
            qa[dc][f][1] = f2tf(q_hi[dc * 8 + qid]);
            qa[dc][f][2] = f2tf(q_lo[dc * 8 + qid + 4]);
            qa[dc][f][3] = f2tf(q_hi[dc * 8 + qid + 4]);
        }
    }

    float4 O[2][8];
#pragma unroll
    for (int f = 0; f < 2; f++)
#pragma unroll
        for (int dt = 0; dt < 8; dt++) O[f][dt] = make_float4(0.f, 0.f, 0.f, 0.f);
    float mrun[2][2] = {{-1e30f, -1e30f}, {-1e30f, -1e30f}};
    float lrun[2][2] = {{0.f, 0.f}, {0.f, 0.f}};

    // prologue: K(0) -> Ks[0]
#pragma unroll
    for (int r = 0; r < 4; r++) {
        int row = srow + r * 8;
        cpa16(ks_base + (row * 68 + sc4) * 4, kg + (size_t)row * DH + sc4);
    }
    cpa_commit();

    for (int kt = 0; kt < 64; kt++) {
        const int buf = kt & 1;
        // issue V(kt) into Vs (safe: loop-end barrier of kt-1 passed)
#pragma unroll
        for (int r = 0; r < 4; r++) {
            int row = srow + r * 8;
            cpa16(vs_base + (row * 72 + sc4) * 4,
                  vg + (size_t)(kt * 32 + row) * DH + sc4);
        }
        cpa_commit();
        if (kt < 63) {
#pragma unroll
            for (int r = 0; r < 4; r++) {
                int row = srow + r * 8;
                cpa16(ks_base + ((buf ^ 1) * 32 * 68 + row * 68 + sc4) * 4,
                      kg + (size_t)((kt + 1) * 32 + row) * DH + sc4);
            }
            cpa_commit();
            cpa_wait<2>();   // K(kt) ready (V(kt), K(kt+1) pending)
        } else {
            cpa_wait<1>();   // K(63) ready (V(63) pending)
        }
        __syncthreads();

        const float* ksb = &Ks[buf][0];

        // S = Q K^T : B-frags loaded once, used by both m-frags
        float4 S[2][4];
#pragma unroll
        for (int f = 0; f < 2; f++)
#pragma unroll
            for (int nt = 0; nt < 4; nt++) S[f][nt] = make_float4(0.f, 0.f, 0.f, 0.f);
#pragma unroll
        for (int dc = 0; dc < 8; dc++) {
#pragma unroll
            for (int nt = 0; nt < 4; nt++) {
                unsigned b0 = f2tf(ksb[(nt * 8 + gid) * 68 + dc * 8 + qid]);
                unsigned b1 = f2tf(ksb[(nt * 8 + gid) * 68 + dc * 8 + qid + 4]);
                mma_tf32(S[0][nt], qa[dc][0][0], qa[dc][0][1], qa[dc][0][2], qa[dc][0][3], b0, b1);
                mma_tf32(S[1][nt], qa[dc][1][0], qa[dc][1][1], qa[dc][1][2], qa[dc][1][3], b0, b1);
            }
        }

        // bias + online softmax per m-frag
#pragma unroll
        for (int f = 0; f < 2; f++) {
            const __nv_bfloat16* b_lo = bg + (size_t)(r0 + f * 16 + gid) * SS + kt * 32 + qid * 2;
            const __nv_bfloat16* b_hi = b_lo + 8 * SS;
            float mn_lo = mrun[f][0], mn_hi = mrun[f][1];
#pragma unroll
            for (int nt = 0; nt < 4; nt++) {
                float2 blo = __bfloat1622float2(*(const __nv_bfloat162*)(b_lo + nt * 8));
                float2 bhi = __bfloat1622float2(*(const __nv_bfloat162*)(b_hi + nt * 8));
                S[f][nt].x += blo.x; S[f][nt].y += blo.y;
                S[f][nt].z += bhi.x; S[f][nt].w += bhi.y;
                mn_lo = fmaxf(mn_lo, fmaxf(S[f][nt].x, S[f][nt].y));
                mn_hi = fmaxf(mn_hi, fmaxf(S[f][nt].z, S[f][nt].w));
            }
            mn_lo = fmaxf(mn_lo, __shfl_xor_sync(0xffffffffu, mn_lo, 1));
            mn_lo = fmaxf(mn_lo, __shfl_xor_sync(0xffffffffu, mn_lo, 2));
            mn_hi = fmaxf(mn_hi, __shfl_xor_sync(0xffffffffu, mn_hi, 1));
            mn_hi = fmaxf(mn_hi, __shfl_xor_sync(0xffffffffu, mn_hi, 2));

            float fac_lo = __expf(mrun[f][0] - mn_lo);
            float fac_hi = __expf(mrun[f][1] - mn_hi);
            mrun[f][0] = mn_lo; mrun[f][1] = mn_hi;

            float rs_lo = 0.f, rs_hi = 0.f;
            float* p_lo = Ps + (r0 + f * 16 + gid) * 36;
            float* p_hi = p_lo + 8 * 36;
#pragma unroll
            for (int nt = 0; nt < 4; nt++) {
                float p0 = __expf(S[f][nt].x - mn_lo);
                float p1 = __expf(S[f][nt].y - mn_lo);
                float p2 = __expf(S[f][nt].z - mn_hi);
                float p3 = __expf(S[f][nt].w - mn_hi);
                rs_lo += p0 + p1; rs_hi += p2 + p3;
                float2 st;
                st.x = __uint_as_float(f2tf(p0)); st.y = __uint_as_float(f2tf(p1));
                *(float2*)&p_lo[nt * 8 + qid * 2] = st;
                st.x = __uint_as_float(f2tf(p2)); st.y = __uint_as_float(f2tf(p3));
                *(float2*)&p_hi[nt * 8 + qid * 2] = st;
            }
            rs_lo += __shfl_xor_sync(0xffffffffu, rs_lo, 1);
            rs_lo += __shfl_xor_sync(0xffffffffu, rs_lo, 2);
            rs_hi += __shfl_xor_sync(0xffffffffu, rs_hi, 1);
            rs_hi += __shfl_xor_sync(0xffffffffu, rs_hi, 2);
            lrun[f][0] = lrun[f][0] * fac_lo + rs_lo;
            lrun[f][1] = lrun[f][1] * fac_hi + rs_hi;

#pragma unroll
            for (int dt = 0; dt < 8; dt++) {
                O[f][dt].x *= fac_lo; O[f][dt].y *= fac_lo;
                O[f][dt].z *= fac_hi; O[f][dt].w *= fac_hi;
            }
        }
        __syncwarp();

        // V(kt) ready?
        if (kt < 63) cpa_wait<1>(); else cpa_wait<0>();
        __syncthreads();

        // O += P V : B-frags shared across m-frags
#pragma unroll
        for (int kc = 0; kc < 4; kc++) {
            unsigned a[2][4];
#pragma unroll
            for (int f = 0; f < 2; f++) {
                const float* p_lo = Ps + (r0 + f * 16 + gid) * 36;
                const float* p_hi = p_lo + 8 * 36;
                a[f][0] = __float_as_uint(p_lo[kc * 8 + qid]);
                a[f][1] = __float_as_uint(p_hi[kc * 8 + qid]);
                a[f][2] = __float_as_uint(p_lo[kc * 8 + qid + 4]);
                a[f][3] = __float_as_uint(p_hi[kc * 8 + qid + 4]);
            }
#pragma unroll
            for (int dt = 0; dt < 8; dt++) {
                unsigned b0 = f2tf(Vs[(kc * 8 + qid) * 72 + dt * 8 + gid]);
                unsigned b1 = f2tf(Vs[(kc * 8 + qid + 4) * 72 + dt * 8 + gid]);
                mma_tf32(O[0][dt], a[0][0], a[0][1], a[0][2], a[0][3], b0, b1);
                mma_tf32(O[1][dt], a[1][0], a[1][1], a[1][2], a[1][3], b0, b1);
            }
        }
        __syncthreads();   // protect Vs/Ks overwrite next iteration
    }

    // epilogue: normalize, write [b][s][h*64+d]
    const int b_ = bh >> 3, h_ = bh & 7;
#pragma unroll
    for (int f = 0; f < 2; f++) {
        const float inv_lo = 1.f / lrun[f][0];
        const float inv_hi = 1.f / lrun[f][1];
        int row_lo = qt * 128 + r0 + f * 16 + gid;
        float* o_lo = g_attn + (size_t)(b_ * SS + row_lo) * HIDD + h_ * 64;
        float* o_hi = o_lo + 8 * HIDD;
#pragma unroll
        for (int dt = 0; dt < 8; dt++) {
            float2 w;
            w.x = O[f][dt].x * inv_lo; w.y = O[f][dt].y * inv_lo;
            *(float2*)(o_lo + dt * 8 + qid * 2) = w;
            w.x = O[f][dt].z * inv_hi; w.y = O[f][dt].w * inv_hi;
            *(float2*)(o_hi + dt * 8 + qid * 2) = w;
        }
    }
}

// ---------------------------------------------------------------------------
extern "C" void kernel_launch(void* const* d_in, const int* in_sizes, int n_in,
                              void* d_out, int out_size)
{
    const float* q   = (const float*)d_in[0];
    const float* k   = (const float*)d_in[1];
    const float* v   = (const float*)d_in[2];
    const float* ab  = (const float*)d_in[3];
    const float* Wq  = (const float*)d_in[4];
    const float* bq  = (const float*)d_in[5];
    const float* Wk  = (const float*)d_in[6];
    const float* bk  = (const float*)d_in[7];
    const float* Wv  = (const float*)d_in[8];
    const float* bv  = (const float*)d_in[9];
    const float* Wb  = (const float*)d_in[10];
    const float* bbv = (const float*)d_in[11];
    const float* Wo  = (const float*)d_in[12];
    const float* bo  = (const float*)d_in[13];
    float* out = (float*)d_out;

    gemm_qkv<<<dim3(4, 64, 3), 256>>>(q, Wq, bq, k, Wk, bk, v, Wv, bv);
    bias_kernel<<<65536, 256>>>(ab, Wb, bbv);
    attn_kernel<<<512, 128>>>();
    gemm_out<<<dim3(4, 64), 256>>>(Wo, bo, out);
}